// round 1
// baseline (speedup 1.0000x reference)
#include <cuda_runtime.h>
#include <cstdint>
#include <cstdio>

#define BDIM 64
#define TDIM 2048
#define DDIM 256
#define HDIM 256
#define G3   768

// Scratch for the input projection xg = x @ W_ih^T + b_ih : [B*T, 3H] fp32 (402 MB)
__device__ float g_xg[(size_t)BDIM * TDIM * G3];

// ---------------- f32x2 helpers (Blackwell packed fp32) ----------------
__device__ __forceinline__ unsigned long long pk2(float x, float y) {
    unsigned long long r;
    asm("mov.b64 %0, {%1, %2};" : "=l"(r) : "f"(x), "f"(y));
    return r;
}
__device__ __forceinline__ void upk2(unsigned long long p, float& x, float& y) {
    asm("mov.b64 {%0, %1}, %2;" : "=f"(x), "=f"(y) : "l"(p));
}
__device__ __forceinline__ unsigned long long fma2(unsigned long long a,
                                                   unsigned long long b,
                                                   unsigned long long c) {
    unsigned long long d;
    asm("fma.rn.f32x2 %0, %1, %2, %3;" : "=l"(d) : "l"(a), "l"(b), "l"(c));
    return d;
}

// ---------------- Kernel 1: projection GEMM ----------------
// out[bt][n] = sum_k x[bt][k] * W[n][k] + bias[n]
// M = B*T = 131072, N = 768, K = 256. Tiles: BM=64, BN=64, BK=32, 256 thr.
#define BM 64
#define BN 64
#define BK 32

__global__ __launch_bounds__(256) void proj_gemm(const float* __restrict__ x,
                                                 const float* __restrict__ W,
                                                 const float* __restrict__ bias) {
    __shared__ float As[BK][BM + 4];  // [k][m]
    __shared__ float Bs[BK][BN + 4];  // [k][n]
    const int tid = threadIdx.x;
    const int gm = blockIdx.x * BM;
    const int gn = blockIdx.y * BN;
    const int m4 = (tid >> 4) * 4;   // lanes 0..15 share m4 -> coalesced stores
    const int n4 = (tid & 15) * 4;

    unsigned long long acc[4][2];
#pragma unroll
    for (int i = 0; i < 4; i++) { acc[i][0] = 0ull; acc[i][1] = 0ull; }

    for (int kt = 0; kt < DDIM; kt += BK) {
#pragma unroll
        for (int j = 0; j < 2; j++) {
            int idx = tid + j * 256;       // 0..511
            int row = idx >> 3;            // 0..63
            int c4  = (idx & 7) * 4;       // k offset 0..28
            float4 va = *(const float4*)&x[(size_t)(gm + row) * DDIM + kt + c4];
            As[c4 + 0][row] = va.x; As[c4 + 1][row] = va.y;
            As[c4 + 2][row] = va.z; As[c4 + 3][row] = va.w;
            float4 vb = *(const float4*)&W[(size_t)(gn + row) * DDIM + kt + c4];
            Bs[c4 + 0][row] = vb.x; Bs[c4 + 1][row] = vb.y;
            Bs[c4 + 2][row] = vb.z; Bs[c4 + 3][row] = vb.w;
        }
        __syncthreads();
#pragma unroll
        for (int k = 0; k < BK; k++) {
            float4 av = *(const float4*)&As[k][m4];
            float4 bv = *(const float4*)&Bs[k][n4];
            unsigned long long bp0 = pk2(bv.x, bv.y);
            unsigned long long bp1 = pk2(bv.z, bv.w);
            unsigned long long aa;
            aa = pk2(av.x, av.x);
            acc[0][0] = fma2(aa, bp0, acc[0][0]); acc[0][1] = fma2(aa, bp1, acc[0][1]);
            aa = pk2(av.y, av.y);
            acc[1][0] = fma2(aa, bp0, acc[1][0]); acc[1][1] = fma2(aa, bp1, acc[1][1]);
            aa = pk2(av.z, av.z);
            acc[2][0] = fma2(aa, bp0, acc[2][0]); acc[2][1] = fma2(aa, bp1, acc[2][1]);
            aa = pk2(av.w, av.w);
            acc[3][0] = fma2(aa, bp0, acc[3][0]); acc[3][1] = fma2(aa, bp1, acc[3][1]);
        }
        __syncthreads();
    }

    float4 bb = *(const float4*)&bias[gn + n4];
#pragma unroll
    for (int mi = 0; mi < 4; mi++) {
        float o0, o1, o2, o3;
        upk2(acc[mi][0], o0, o1);
        upk2(acc[mi][1], o2, o3);
        float4 o = make_float4(o0 + bb.x, o1 + bb.y, o2 + bb.z, o3 + bb.w);
        *(float4*)&g_xg[(size_t)(gm + m4 + mi) * G3 + gn + n4] = o;
    }
}

// ---------------- Kernel 2: persistent cluster recurrence ----------------
// 32 clusters of 4 CTAs. Cluster = batch group of 2 rows; CTA rank owns 64 h
// indices (192 W_hh rows in smem). h exchanged each step via DSMEM + cluster bar.
#define RTH 384
#define HC 64
#define NR 192
#define WST 260   // row stride (floats): 1040 B, conflict-free for LDS.128
#define CLSZ 4

__device__ __forceinline__ float sigm_f(float x) { return 1.f / (1.f + __expf(-x)); }
__device__ __forceinline__ float tanh_f(float x) { return 1.f - 2.f / (__expf(2.f * x) + 1.f); }

__device__ __forceinline__ void st_dsmem_f2(uint32_t saddr, uint32_t rank, float2 v) {
    uint32_t raddr;
    asm volatile("mapa.shared::cluster.u32 %0, %1, %2;" : "=r"(raddr) : "r"(saddr), "r"(rank));
    unsigned long long p;
    asm("mov.b64 %0, {%1, %2};" : "=l"(p) : "f"(v.x), "f"(v.y));
    asm volatile("st.shared::cluster.u64 [%0], %1;" :: "r"(raddr), "l"(p) : "memory");
}
__device__ __forceinline__ void cluster_barrier() {
    asm volatile("barrier.cluster.arrive.aligned;" ::: "memory");
    asm volatile("barrier.cluster.wait.aligned;" ::: "memory");
}

__global__ __launch_bounds__(RTH, 1) void gru_rec(const float* __restrict__ h0,
                                                  const float* __restrict__ W_hh,
                                                  const float* __restrict__ b_hh,
                                                  float* __restrict__ hs,
                                                  float* __restrict__ hT) {
    extern __shared__ float sm[];
    float*  ws   = sm;                              // 192*260 floats
    float2* hp0  = (float2*)(sm + NR * WST);        // 256 float2 (h for 2 batches)
    float2* hp1  = hp0 + HDIM;                      // 256 float2
    float2* red  = hp1 + HDIM;                      // 192 float2
    float2* hgb  = red + NR;                        // 192 float2
    float*  xgs  = (float*)(hgb + NR);              // 384 floats

    uint32_t rank;
    asm("mov.u32 %0, %%cluster_ctarank;" : "=r"(rank));
    const int tid = threadIdx.x;
    const int bg = blockIdx.x >> 2;
    const int b0 = bg * 2;

    // Load this CTA's 192 W_hh rows into smem (rows g*256 + rank*64 + il)
    for (int i = tid; i < NR * (HDIM / 4); i += RTH) {
        int lr = i >> 6;
        int k4 = (i & 63) * 4;
        int g = lr / HC, il = lr - g * HC;
        int grow = g * HDIM + (int)rank * HC + il;
        float4 v = *(const float4*)&W_hh[(size_t)grow * HDIM + k4];
        *(float4*)&ws[lr * WST + k4] = v;
    }
    // Init h buffer 0
    for (int i = tid; i < HDIM; i += RTH)
        hp0[i] = make_float2(h0[(size_t)b0 * HDIM + i], h0[(size_t)(b0 + 1) * HDIM + i]);

    float bhr = 0.f, bhz = 0.f, bhn = 0.f;
    if (tid < HC) {
        bhr = b_hh[rank * HC + tid];
        bhz = b_hh[HDIM + rank * HC + tid];
        bhn = b_hh[2 * HDIM + rank * HC + tid];
    }
    __syncthreads();
    cluster_barrier();

    const int half = tid / NR;        // 0/1 : k-half AND batch index for xg prefetch
    const int r = tid - half * NR;    // row 0..191
    const int kb = half * (HDIM / 2); // 0 or 128
    const int pg = r / HC, pil = r - pg * HC;
    const size_t xg_base = ((size_t)(b0 + half) * TDIM) * G3
                         + (size_t)pg * HDIM + (size_t)rank * HC + pil;

    for (int t = 0; t < TDIM; t++) {
        const int cur = t & 1;
        float2* hcb = cur ? hp1 : hp0;
        float2* hnb = cur ? hp0 : hp1;

        // Prefetch this thread's xg element (hidden under the matvec)
        float xv = g_xg[xg_base + (size_t)t * G3];

        const float*  wrow = ws + r * WST + kb;
        const float2* hc   = hcb + kb;
        float a0 = 0.f, a1 = 0.f;
#pragma unroll
        for (int k = 0; k < HDIM / 2; k += 4) {
            float4 w  = *(const float4*)(wrow + k);
            float4 hA = *(const float4*)(hc + k);       // h[k],h[k+1] for both batches
            float4 hB = *(const float4*)(hc + k + 2);
            a0 += w.x * hA.x; a1 += w.x * hA.y;
            a0 += w.y * hA.z; a1 += w.y * hA.w;
            a0 += w.z * hB.x; a1 += w.z * hB.y;
            a0 += w.w * hB.z; a1 += w.w * hB.w;
        }
        if (half) red[r] = make_float2(a0, a1);
        xgs[tid] = xv;
        __syncthreads();
        if (!half) {
            float2 p = red[r];
            hgb[r] = make_float2(a0 + p.x, a1 + p.y);
        }
        __syncthreads();

        if (tid < HC) {
            const int il = tid;
            float2 hr = hgb[il], hz = hgb[HC + il], hn = hgb[2 * HC + il];
            float2 hv = hcb[rank * HC + il];
            float xr0 = xgs[il],      xz0 = xgs[HC + il],      xn0 = xgs[2 * HC + il];
            float xr1 = xgs[NR + il], xz1 = xgs[NR + HC + il], xn1 = xgs[NR + 2 * HC + il];

            float rg0 = sigm_f(xr0 + hr.x + bhr);
            float zg0 = sigm_f(xz0 + hz.x + bhz);
            float ng0 = tanh_f(xn0 + rg0 * (hn.x + bhn));
            float h0n = (1.f - zg0) * ng0 + zg0 * hv.x;

            float rg1 = sigm_f(xr1 + hr.y + bhr);
            float zg1 = sigm_f(xz1 + hz.y + bhz);
            float ng1 = tanh_f(xn1 + rg1 * (hn.y + bhn));
            float h1n = (1.f - zg1) * ng1 + zg1 * hv.y;

            float2 nh = make_float2(h0n, h1n);
            int gi = (int)rank * HC + il;
            uint32_t saddr = (uint32_t)__cvta_generic_to_shared(&hnb[gi]);
#pragma unroll
            for (uint32_t dr = 0; dr < CLSZ; dr++) st_dsmem_f2(saddr, dr, nh);

            hs[((size_t)b0 * TDIM + t) * HDIM + gi] = h0n;
            hs[((size_t)(b0 + 1) * TDIM + t) * HDIM + gi] = h1n;
            if (t == TDIM - 1) {
                hT[(size_t)b0 * HDIM + gi] = h0n;
                hT[(size_t)(b0 + 1) * HDIM + gi] = h1n;
            }
        }
        // One cluster barrier per step: publishes DSMEM h writes (release/acquire)
        // and prevents next-step buffer reuse hazards.
        cluster_barrier();
    }
}

// ---------------- launch ----------------
extern "C" void kernel_launch(void* const* d_in, const int* in_sizes, int n_in,
                              void* d_out, int out_size) {
    (void)in_sizes; (void)n_in; (void)out_size;
    const float* x    = (const float*)d_in[0];
    const float* h0   = (const float*)d_in[1];
    const float* W_ih = (const float*)d_in[2];
    const float* W_hh = (const float*)d_in[3];
    const float* b_ih = (const float*)d_in[4];
    const float* b_hh = (const float*)d_in[5];
    float* out = (float*)d_out;
    float* hs = out;
    float* hT = out + (size_t)BDIM * TDIM * HDIM;

    // K1: projection GEMM -> g_xg
    dim3 g1((BDIM * TDIM) / BM, G3 / BN);
    proj_gemm<<<g1, 256>>>(x, W_ih, b_ih);

    // K2: persistent cluster recurrence
    const int smem_bytes = (NR * WST + 2 * 2 * HDIM + 2 * 2 * NR + RTH) * 4; // 208384
    cudaFuncSetAttribute(gru_rec, cudaFuncAttributeMaxDynamicSharedMemorySize, smem_bytes);

    cudaLaunchConfig_t cfg = {};
    cfg.gridDim = dim3(128, 1, 1);
    cfg.blockDim = dim3(RTH, 1, 1);
    cfg.dynamicSmemBytes = smem_bytes;
    cfg.stream = 0;
    cudaLaunchAttribute attrs[1];
    attrs[0].id = cudaLaunchAttributeClusterDimension;
    attrs[0].val.clusterDim.x = CLSZ;
    attrs[0].val.clusterDim.y = 1;
    attrs[0].val.clusterDim.z = 1;
    cfg.attrs = attrs;
    cfg.numAttrs = 1;
    cudaLaunchKernelEx(&cfg, gru_rec, h0, W_hh, b_hh, hs, hT);
}